// round 15
// baseline (speedup 1.0000x reference)
#include <cuda_runtime.h>
#include <cuda_fp16.h>
#include <mma.h>
#include <cstdint>

using namespace nvcuda;

// Problem constants
#define NN      50000
#define NN_PAD  50048            // 128 * 391
#define EE      640000
#define HID     128
#define RR      5
#define NHEADS  8
#define HDIM    16
#define NCOLS   (RR*3*HID)       // 1920
#define NPLANES (RR*3)           // 15
#define NKEYS   (NN*RR)          // 250000
#define NSBLK   245              // ceil(NKEYS/1024)
#define LN_EPS  1e-5f

// ---------------- static device scratch ----------------
__device__ __half g_wbigh[HID * NCOLS];              // [k][c] packed QKV weights (fp16)
__device__ __half g_wprojh[HID * HID];               // [i][j] transposed out_proj (fp16)
__device__ __half g_xh[(size_t)NN * HID];            // fp16 copy of x
__device__ __half g_acch[(size_t)NN * HID];          // attention output (fp16, feeds proj GEMM)
// plane-separated QKV: plane p = r*3+t (t: 0=Q,1=K,2=V), row-major [NN_PAD][128]
__device__ __half g_qkvh[(size_t)NPLANES * NN_PAD * HID];
__device__ float  g_ev[(size_t)EE * NHEADS];         // exp(logit) per sorted-edge/head
__device__ float  g_proj[(size_t)NN_PAD * HID];      // out_proj result (padded rows)
__device__ int    g_src[EE];
__device__ int    g_dst[EE];
__device__ int    g_rel[EE];
__device__ int    g_is64;
// counting sort by key = r*NN + dst  (relation-major: edge list is relation-blocked)
__device__ int    g_cnt[NKEYS];
__device__ int    g_offtmp[NKEYS];
__device__ int    g_bsum[256];
__device__ int    g_boff[256];
__device__ int    g_off[NKEYS + 1];
__device__ int    g_cur[NKEYS];
__device__ int    g_srcs[EE];
__device__ int    g_key[EE];

// ---------------- convert x to fp16 + zero sort counters ---------------- (launch 0)
__global__ void roundx_kernel(const float* __restrict__ x) {
    int i = blockIdx.x * blockDim.x + threadIdx.x;   // float4 index
    if (i < NN * HID / 4) {
        float4 v = ((const float4*)x)[i];
        __half2* dst = (__half2*)(g_xh + (size_t)i * 4);
        dst[0] = __floats2half2_rn(v.x, v.y);
        dst[1] = __floats2half2_rn(v.z, v.w);
    }
    int stride = gridDim.x * blockDim.x;
    for (int j = i; j < NKEYS; j += stride) g_cnt[j] = 0;
}

// ---------------- repack weights to fp16 ---------------- (launch 1)
__global__ void repack_kernel(const float* __restrict__ WQ,
                              const float* __restrict__ WK,
                              const float* __restrict__ WV,
                              const float* __restrict__ Wp) {
    int idx = blockIdx.x * blockDim.x + threadIdx.x;
    if (idx < HID * NCOLS) {
        int k = idx / NCOLS;
        int c = idx % NCOLS;
        int r = c / 384;
        int rem = c % 384;
        int t = rem / 128;
        int hd = rem % 128;
        int h = hd / HDIM;
        int d = hd % HDIM;
        const float* W = (t == 0) ? WQ : (t == 1) ? WK : WV;
        g_wbigh[idx] = __float2half_rn(W[(((size_t)(r * NHEADS + h) * HID) + k) * HDIM + d]);
    }
    if (idx < HID * HID) {
        int i = idx / HID;
        int j = idx % HID;
        g_wprojh[idx] = __float2half_rn(Wp[j * HID + i]);
    }
}

// ---------------- detect int64 vs int32 edge_index ---------------- (launch 2)
__global__ void detect_kernel(const int* __restrict__ ei_raw) {
    int l = threadIdx.x;
    int zeros = 0;
    #pragma unroll
    for (int j = 0; j < 16; j++) {
        int i = l * 16 + j;
        if (ei_raw[2 * i + 1] == 0) zeros++;
    }
    #pragma unroll
    for (int off = 16; off >= 1; off >>= 1)
        zeros += __shfl_xor_sync(0xFFFFFFFFu, zeros, off);
    if (l == 0) g_is64 = (zeros > 500) ? 1 : 0;
}

// ==================== fp16 wmma GEMM, double-buffered cp.async ====================
#define BK      32
#define A_LDH   40
#define B_LDH   136
#define STAGE_H (128 * A_LDH + BK * B_LDH)            // 9472 halves; 2 stages = 37888 B
#define S_LDM   68

__device__ __forceinline__ void cp16(uint32_t saddr, const void* g, bool pred) {
    int sz = pred ? 16 : 0;
    asm volatile("cp.async.cg.shared.global [%0], [%1], 16, %2;"
                 :: "r"(saddr), "l"(g), "r"(sz));
}
#define CP_COMMIT() asm volatile("cp.async.commit_group;")
#define CP_WAIT1()  asm volatile("cp.async.wait_group 1;")
#define CP_WAIT0()  asm volatile("cp.async.wait_group 0;")

__device__ __forceinline__ void gemm_issue(const __half* __restrict__ A,
                                           const __half* __restrict__ B,
                                           __half* As, __half* Bs,
                                           int tid, int bm, int bn,
                                           int kc, int M, int Ncols) {
    uint32_t sA = (uint32_t)__cvta_generic_to_shared(As);
    uint32_t sB = (uint32_t)__cvta_generic_to_shared(Bs);
    #pragma unroll
    for (int j = 0; j < 2; j++) {
        int f = tid + 256 * j;
        int m = f >> 2;
        int c8 = f & 3;
        int gm = bm + m;
        cp16(sA + (m * A_LDH + c8 * 8) * 2,
             A + (size_t)gm * HID + kc + c8 * 8, gm < M);
    }
    #pragma unroll
    for (int j = 0; j < 2; j++) {
        int f = tid + 256 * j;
        int k = f >> 4;
        int c8 = f & 15;
        cp16(sB + (k * B_LDH + c8 * 8) * 2,
             B + (size_t)(kc + k) * Ncols + bn + c8 * 8, true);
    }
    CP_COMMIT();
}

__device__ __forceinline__ void gemm_compute(
    const __half* As, const __half* Bs, int wm, int wn,
    wmma::fragment<wmma::accumulator, 16, 16, 16, float> (&cfrag)[2][4]) {
    #pragma unroll
    for (int ks = 0; ks < BK; ks += 16) {
        wmma::fragment<wmma::matrix_a, 16, 16, 16, __half, wmma::row_major> afrag[2];
        wmma::fragment<wmma::matrix_b, 16, 16, 16, __half, wmma::row_major> bfrag[4];
        #pragma unroll
        for (int i = 0; i < 2; i++)
            wmma::load_matrix_sync(afrag[i], &As[(wm * 32 + i * 16) * A_LDH + ks], A_LDH);
        #pragma unroll
        for (int j = 0; j < 4; j++)
            wmma::load_matrix_sync(bfrag[j], &Bs[ks * B_LDH + wn * 64 + j * 16], B_LDH);
        #pragma unroll
        for (int i = 0; i < 2; i++)
            #pragma unroll
            for (int j = 0; j < 4; j++)
                wmma::mma_sync(cfrag[i][j], afrag[i], bfrag[j], cfrag[i][j]);
    }
}

// HOUT=true: writes fp16 into plane blockIdx.y of g_qkvh ([NN_PAD][128] row-major).
template<bool HOUT>
__device__ __forceinline__ void gemm_tc_body(const __half* __restrict__ A,
                                             const __half* __restrict__ B,
                                             void* __restrict__ Cv,
                                             int M, int Ncols) {
    __shared__ alignas(16) __half smem[2 * STAGE_H];
    __half* As0 = smem;
    __half* Bs0 = smem + 128 * A_LDH;
    __half* As1 = smem + STAGE_H;
    __half* Bs1 = smem + STAGE_H + 128 * A_LDH;

    int tid = threadIdx.x;
    int wid = tid >> 5;
    int lane = tid & 31;
    int wm = wid & 3;
    int wn = wid >> 2;
    int bm = blockIdx.x * 128;
    int bn = blockIdx.y * 128;

    wmma::fragment<wmma::accumulator, 16, 16, 16, float> cfrag[2][4];
    #pragma unroll
    for (int i = 0; i < 2; i++)
        #pragma unroll
        for (int j = 0; j < 4; j++)
            wmma::fill_fragment(cfrag[i][j], 0.0f);

    gemm_issue(A, B, As0, Bs0, tid, bm, bn, 0, M, Ncols);
    gemm_issue(A, B, As1, Bs1, tid, bm, bn, BK, M, Ncols);
    CP_WAIT1(); __syncthreads();
    gemm_compute(As0, Bs0, wm, wn, cfrag);
    __syncthreads();
    gemm_issue(A, B, As0, Bs0, tid, bm, bn, 2 * BK, M, Ncols);
    CP_WAIT1(); __syncthreads();
    gemm_compute(As1, Bs1, wm, wn, cfrag);
    __syncthreads();
    gemm_issue(A, B, As1, Bs1, tid, bm, bn, 3 * BK, M, Ncols);
    CP_WAIT1(); __syncthreads();
    gemm_compute(As0, Bs0, wm, wn, cfrag);
    __syncthreads();
    CP_WAIT0(); __syncthreads();
    gemm_compute(As1, Bs1, wm, wn, cfrag);

    if (HOUT) {
        __syncthreads();
        // Plane-separated output: plane = blockIdx.y, row-major [NN_PAD][128]
        __half* Ch = (__half*)Cv + (size_t)blockIdx.y * NN_PAD * HID;
        float* stage = (float*)smem;
        float* ws = stage + wid * 16 * S_LDM;
        #pragma unroll
        for (int i = 0; i < 2; i++) {
            #pragma unroll
            for (int j = 0; j < 4; j++)
                wmma::store_matrix_sync(ws + j * 16, cfrag[i][j], S_LDM, wmma::mem_row_major);
            __syncwarp();
            int gm = bm + wm * 32 + i * 16;
            int gn = wn * 64;
            #pragma unroll
            for (int rr = 0; rr < 16; rr++) {
                float2 v = *(float2*)(ws + rr * S_LDM + lane * 2);
                *(__half2*)(Ch + (size_t)(gm + rr) * HID + gn + lane * 2) =
                    __floats2half2_rn(v.x, v.y);
            }
            __syncwarp();
        }
    } else {
        float* C = (float*)Cv;
        #pragma unroll
        for (int i = 0; i < 2; i++) {
            int gm = bm + wm * 32 + i * 16;
            #pragma unroll
            for (int j = 0; j < 4; j++) {
                int gn = bn + wn * 64 + j * 16;
                wmma::store_matrix_sync(C + (size_t)gm * Ncols + gn, cfrag[i][j],
                                        Ncols, wmma::mem_row_major);
            }
        }
    }
}

__global__ void __launch_bounds__(256, 2) gemm_qkv_kernel() {
    gemm_tc_body<true>(g_xh, g_wbigh, g_qkvh, NN, NCOLS);
}
__global__ void __launch_bounds__(256, 2) gemm_proj_kernel() {
    gemm_tc_body<false>(g_acch, g_wprojh, g_proj, NN, HID);
}

// ---------------- fused convert + histogram (key = r*NN + dst) ----------------
__global__ void converthist_kernel(const int* __restrict__ ei_raw,
                                   const int* __restrict__ et_raw) {
    int i = blockIdx.x * blockDim.x + threadIdx.x;
    if (i >= EE) return;
    int s, d, r;
    if (g_is64) {
        s = ei_raw[2 * i];
        d = ei_raw[2 * (EE + i)];
        r = et_raw[2 * i];
    } else {
        s = ei_raw[i];
        d = ei_raw[EE + i];
        r = et_raw[i];
    }
    s = min(max(s, 0), NN - 1);
    d = min(max(d, 0), NN - 1);
    r = min(max(r, 0), RR - 1);
    g_src[i] = s;
    g_dst[i] = d;
    g_rel[i] = r;
    atomicAdd(&g_cnt[r * NN + d], 1);
}

// multi-block scan
__global__ void scan_p1_kernel() {
    __shared__ int wsum[8];
    int b = blockIdx.x;
    int t = threadIdx.x;
    int base = b * 1024 + t * 4;
    int4 v = make_int4(0, 0, 0, 0);
    if (base + 3 < NKEYS) {
        v = *(const int4*)&g_cnt[base];
    } else {
        if (base + 0 < NKEYS) v.x = g_cnt[base + 0];
        if (base + 1 < NKEYS) v.y = g_cnt[base + 1];
        if (base + 2 < NKEYS) v.z = g_cnt[base + 2];
        if (base + 3 < NKEYS) v.w = g_cnt[base + 3];
    }
    int tsum = v.x + v.y + v.z + v.w;
    int lane = t & 31, w = t >> 5;
    int sc = tsum;
    #pragma unroll
    for (int off = 1; off < 32; off <<= 1) {
        int n = __shfl_up_sync(0xFFFFFFFFu, sc, off);
        if (lane >= off) sc += n;
    }
    if (lane == 31) wsum[w] = sc;
    __syncthreads();
    if (t == 0) {
        int run = 0;
        #pragma unroll
        for (int i = 0; i < 8; i++) { int tmp = wsum[i]; wsum[i] = run; run += tmp; }
        g_bsum[b] = run;
    }
    __syncthreads();
    int excl = wsum[w] + sc - tsum;
    int4 o;
    o.x = excl;
    o.y = excl + v.x;
    o.z = excl + v.x + v.y;
    o.w = excl + v.x + v.y + v.z;
    if (base + 3 < NKEYS) {
        *(int4*)&g_offtmp[base] = o;
    } else {
        if (base + 0 < NKEYS) g_offtmp[base + 0] = o.x;
        if (base + 1 < NKEYS) g_offtmp[base + 1] = o.y;
        if (base + 2 < NKEYS) g_offtmp[base + 2] = o.z;
        if (base + 3 < NKEYS) g_offtmp[base + 3] = o.w;
    }
}

__global__ void scan_p2_kernel() {
    __shared__ int wsum[8];
    int t = threadIdx.x;
    int val = (t < NSBLK) ? g_bsum[t] : 0;
    int lane = t & 31, w = t >> 5;
    int sc = val;
    #pragma unroll
    for (int off = 1; off < 32; off <<= 1) {
        int n = __shfl_up_sync(0xFFFFFFFFu, sc, off);
        if (lane >= off) sc += n;
    }
    if (lane == 31) wsum[w] = sc;
    __syncthreads();
    if (t == 0) {
        int run = 0;
        #pragma unroll
        for (int i = 0; i < 8; i++) { int tmp = wsum[i]; wsum[i] = run; run += tmp; }
    }
    __syncthreads();
    int excl = wsum[w] + sc - val;
    if (t < NSBLK) g_boff[t] = excl;
}

__global__ void scan_p3_kernel() {
    int i = blockIdx.x * blockDim.x + threadIdx.x;
    if (i < NKEYS) {
        int v = g_offtmp[i] + g_boff[i >> 10];
        g_off[i] = v;
        g_cur[i] = v;
    }
    if (i == 0) g_off[NKEYS] = EE;
}

__global__ void scatter_kernel() {
    int i = blockIdx.x * blockDim.x + threadIdx.x;
    if (i < EE) {
        int key = g_rel[i] * NN + g_dst[i];
        int pos = atomicAdd(&g_cur[key], 1);
        g_srcs[pos] = g_src[i];
        g_key[pos]  = key;
    }
}

// ---------------- pass 1: warp per sorted edge — exp(logit), plane gathers ----------------
// Edge list is relation-blocked: active K plane (12.8MB) stays L2-resident.
__global__ void edge_ev_kernel() {
    int p = (blockIdx.x * blockDim.x + threadIdx.x) >> 5;
    int l = threadIdx.x & 31;
    if (p >= EE) return;
    int key = g_key[p];
    int src = g_srcs[p];
    int r = key / NN;
    int dst = key - r * NN;

    const __half* qp = g_qkvh + ((size_t)(r * 3 + 0) * NN_PAD + dst) * HID;
    const __half* kp = g_qkvh + ((size_t)(r * 3 + 1) * NN_PAD + src) * HID;
    uint2 qraw = *(const uint2*)(qp + l * 4);
    uint2 kraw = *(const uint2*)(kp + l * 4);
    float2 q0 = __half22float2(*(__half2*)&qraw.x);
    float2 q1 = __half22float2(*(__half2*)&qraw.y);
    float2 k0 = __half22float2(*(__half2*)&kraw.x);
    float2 k1 = __half22float2(*(__half2*)&kraw.y);
    float pd = q0.x * k0.x + q0.y * k0.y + q1.x * k1.x + q1.y * k1.y;
    pd += __shfl_xor_sync(0xFFFFFFFFu, pd, 1);
    pd += __shfl_xor_sync(0xFFFFFFFFu, pd, 2);
    float ev = expf(pd * 0.25f);
    if ((l & 3) == 0) g_ev[(size_t)p * NHEADS + (l >> 2)] = ev;
}

// ---------------- pass 2: warp per dst — segmented accumulation, plane V gathers ----------------
__global__ void seg_accum_kernel() {
    int n = (blockIdx.x * blockDim.x + threadIdx.x) >> 5;
    int l = threadIdx.x & 31;
    if (n >= NN) return;
    int h = l >> 2;

    float4 out = make_float4(0.f, 0.f, 0.f, 0.f);
    #pragma unroll
    for (int r = 0; r < RR; r++) {
        int e0 = g_off[r * NN + n];
        int e1 = g_off[r * NN + n + 1];   // contiguous within relation block (dst-major inside r)
        if (e0 >= e1) continue;
        const __half* vplane = g_qkvh + (size_t)(r * 3 + 2) * NN_PAD * HID;
        float sum = 0.0f;
        float4 acc = make_float4(0.f, 0.f, 0.f, 0.f);
        #pragma unroll 4
        for (int e = e0; e < e1; e++) {
            int src = g_srcs[e];
            float ev = g_ev[(size_t)e * NHEADS + h];
            uint2 vraw = *(const uint2*)(vplane + (size_t)src * HID + l * 4);
            float2 v0 = __half22float2(*(__half2*)&vraw.x);
            float2 v1 = __half22float2(*(__half2*)&vraw.y);
            sum += ev;
            acc.x += ev * v0.x;
            acc.y += ev * v0.y;
            acc.z += ev * v1.x;
            acc.w += ev * v1.y;
        }
        float inv = 1.0f / (sum + 1e-12f);
        out.x += acc.x * inv;
        out.y += acc.y * inv;
        out.z += acc.z * inv;
        out.w += acc.w * inv;
    }
    __half2* dst = (__half2*)(g_acch + (size_t)n * HID + l * 4);
    dst[0] = __floats2half2_rn(out.x, out.y);
    dst[1] = __floats2half2_rn(out.z, out.w);
}

// ---------------- bias + residual + LayerNorm ----------------
__global__ void ln_kernel(const float* __restrict__ x,
                          const float* __restrict__ pb,
                          const float* __restrict__ gamma,
                          const float* __restrict__ beta,
                          float* __restrict__ out) {
    int n = (blockIdx.x * blockDim.x + threadIdx.x) >> 5;
    int l = threadIdx.x & 31;
    if (n >= NN) return;
    size_t base = (size_t)n * HID + l * 4;

    float4 p = *(const float4*)(g_proj + base);
    float4 xx = *(const float4*)(x + base);
    float4 b = *(const float4*)(pb + l * 4);
    float4 h;
    h.x = p.x + b.x + xx.x;
    h.y = p.y + b.y + xx.y;
    h.z = p.z + b.z + xx.z;
    h.w = p.w + b.w + xx.w;

    float s = h.x + h.y + h.z + h.w;
    #pragma unroll
    for (int off = 16; off >= 1; off >>= 1) s += __shfl_xor_sync(0xFFFFFFFFu, s, off);
    float mu = s * (1.0f / HID);

    float dx = h.x - mu, dy = h.y - mu, dz = h.z - mu, dw = h.w - mu;
    float v = dx * dx + dy * dy + dz * dz + dw * dw;
    #pragma unroll
    for (int off = 16; off >= 1; off >>= 1) v += __shfl_xor_sync(0xFFFFFFFFu, v, off);
    float inv = rsqrtf(v * (1.0f / HID) + LN_EPS);

    float4 g = *(const float4*)(gamma + l * 4);
    float4 be = *(const float4*)(beta + l * 4);
    float4 o;
    o.x = dx * inv * g.x + be.x;
    o.y = dy * inv * g.y + be.y;
    o.z = dz * inv * g.z + be.z;
    o.w = dw * inv * g.w + be.w;
    *(float4*)(out + base) = o;
}

// ---------------- launch ----------------
extern "C" void kernel_launch(void* const* d_in, const int* in_sizes, int n_in,
                              void* d_out, int out_size) {
    const float* x     = (const float*)d_in[0];
    const int*   ei    = (const int*)d_in[1];
    const int*   et    = (const int*)d_in[2];
    const float* WQ    = (const float*)d_in[3];
    const float* WK    = (const float*)d_in[4];
    const float* WV    = (const float*)d_in[5];
    const float* Wp    = (const float*)d_in[7];
    const float* pb    = (const float*)d_in[8];
    const float* gamma = (const float*)d_in[9];
    const float* beta  = (const float*)d_in[10];
    float* out = (float*)d_out;

    roundx_kernel<<<(NN * HID / 4 + 255) / 256, 256>>>(x);             // 0 (also zeros g_cnt)
    repack_kernel<<<(HID * NCOLS + 255) / 256, 256>>>(WQ, WK, WV, Wp); // 1
    detect_kernel<<<1, 32>>>(ei);                                      // 2

    dim3 g1(NN_PAD / 128, NCOLS / 128);                                // 391 x 15
    gemm_qkv_kernel<<<g1, 256>>>();                                    // 3  <-- profiled slot

    converthist_kernel<<<(EE + 255) / 256, 256>>>(ei, et);             // 4
    scan_p1_kernel<<<NSBLK, 256>>>();                                  // 5
    scan_p2_kernel<<<1, 256>>>();                                      // 6
    scan_p3_kernel<<<(NKEYS + 255) / 256, 256>>>();                    // 7
    scatter_kernel<<<(EE + 255) / 256, 256>>>();                       // 8

    int ev_blocks = (EE * 32 + 255) / 256;                             // 80000
    edge_ev_kernel<<<ev_blocks, 256>>>();                              // 9

    int nwarp_blocks = (NN * 32 + 255) / 256;                          // 6250
    seg_accum_kernel<<<nwarp_blocks, 256>>>();                         // 10

    dim3 g2(NN_PAD / 128, 1);                                          // 391 x 1
    gemm_proj_kernel<<<g2, 256>>>();                                   // 11

    ln_kernel<<<nwarp_blocks, 256>>>(x, pb, gamma, beta, out);         // 12
}

// round 16
// speedup vs baseline: 1.1269x; 1.1269x over previous
#include <cuda_runtime.h>
#include <cuda_fp16.h>
#include <mma.h>
#include <cstdint>

using namespace nvcuda;

// Problem constants
#define NN      50000
#define NN_PAD  50048            // 128 * 391
#define EE      640000
#define HID     128
#define RR      5
#define NHEADS  8
#define HDIM    16
#define NCOLS   (RR*3*HID)       // 1920
#define NPLANES (RR*3)           // 15
#define NKEYS   (NN*RR)          // 250000
#define NSBLK   245              // ceil(NKEYS/1024)
#define LN_EPS  1e-5f

// ---------------- static device scratch ----------------
__device__ __half g_wbigh[HID * NCOLS];              // [k][c] packed QKV weights (fp16)
__device__ __half g_wprojh[HID * HID];               // [i][j] transposed out_proj (fp16)
__device__ __half g_xh[(size_t)NN * HID];            // fp16 copy of x
__device__ __half g_acch[(size_t)NN * HID];          // attention output (fp16, feeds proj GEMM)
// plane-separated QKV: plane p = r*3+t (t: 0=Q,1=K,2=V), row-major [NN_PAD][128]
__device__ __half g_qkvh[(size_t)NPLANES * NN_PAD * HID];
__device__ float  g_ev[(size_t)EE * NHEADS];         // exp(logit) per sorted-edge/head
__device__ float  g_proj[(size_t)NN_PAD * HID];      // out_proj result (padded rows)
__device__ int    g_src[EE];
__device__ int    g_dst[EE];
__device__ int    g_rel[EE];
__device__ int    g_is64;
// counting sort by key = r*NN + dst  (relation-major: edge list is relation-blocked)
__device__ int    g_cnt[NKEYS];
__device__ int    g_offtmp[NKEYS];
__device__ int    g_bsum[256];
__device__ int    g_boff[256];
__device__ int    g_off[NKEYS + 1];
__device__ int    g_cur[NKEYS];
__device__ int    g_srcs[EE];
__device__ int    g_key[EE];

// ---------------- convert x to fp16 + zero sort counters ---------------- (launch 0)
__global__ void roundx_kernel(const float* __restrict__ x) {
    int i = blockIdx.x * blockDim.x + threadIdx.x;   // float4 index
    if (i < NN * HID / 4) {
        float4 v = ((const float4*)x)[i];
        __half2* dst = (__half2*)(g_xh + (size_t)i * 4);
        dst[0] = __floats2half2_rn(v.x, v.y);
        dst[1] = __floats2half2_rn(v.z, v.w);
    }
    int stride = gridDim.x * blockDim.x;
    for (int j = i; j < NKEYS; j += stride) g_cnt[j] = 0;
}

// ---------------- repack weights to fp16 ---------------- (launch 1)
__global__ void repack_kernel(const float* __restrict__ WQ,
                              const float* __restrict__ WK,
                              const float* __restrict__ WV,
                              const float* __restrict__ Wp) {
    int idx = blockIdx.x * blockDim.x + threadIdx.x;
    if (idx < HID * NCOLS) {
        int k = idx / NCOLS;
        int c = idx % NCOLS;
        int r = c / 384;
        int rem = c % 384;
        int t = rem / 128;
        int hd = rem % 128;
        int h = hd / HDIM;
        int d = hd % HDIM;
        const float* W = (t == 0) ? WQ : (t == 1) ? WK : WV;
        g_wbigh[idx] = __float2half_rn(W[(((size_t)(r * NHEADS + h) * HID) + k) * HDIM + d]);
    }
    if (idx < HID * HID) {
        int i = idx / HID;
        int j = idx % HID;
        g_wprojh[idx] = __float2half_rn(Wp[j * HID + i]);
    }
}

// ---------------- detect int64 vs int32 edge_index ---------------- (launch 2)
__global__ void detect_kernel(const int* __restrict__ ei_raw) {
    int l = threadIdx.x;
    int zeros = 0;
    #pragma unroll
    for (int j = 0; j < 16; j++) {
        int i = l * 16 + j;
        if (ei_raw[2 * i + 1] == 0) zeros++;
    }
    #pragma unroll
    for (int off = 16; off >= 1; off >>= 1)
        zeros += __shfl_xor_sync(0xFFFFFFFFu, zeros, off);
    if (l == 0) g_is64 = (zeros > 500) ? 1 : 0;
}

// ==================== fp16 wmma GEMM, double-buffered cp.async ====================
#define BK      32
#define A_LDH   40
#define B_LDH   136
#define STAGE_H (128 * A_LDH + BK * B_LDH)            // 9472 halves; 2 stages = 37888 B
#define S_LDM   68

__device__ __forceinline__ void cp16(uint32_t saddr, const void* g, bool pred) {
    int sz = pred ? 16 : 0;
    asm volatile("cp.async.cg.shared.global [%0], [%1], 16, %2;"
                 :: "r"(saddr), "l"(g), "r"(sz));
}
#define CP_COMMIT() asm volatile("cp.async.commit_group;")
#define CP_WAIT1()  asm volatile("cp.async.wait_group 1;")
#define CP_WAIT0()  asm volatile("cp.async.wait_group 0;")

__device__ __forceinline__ void gemm_issue(const __half* __restrict__ A,
                                           const __half* __restrict__ B,
                                           __half* As, __half* Bs,
                                           int tid, int bm, int bn,
                                           int kc, int M, int Ncols) {
    uint32_t sA = (uint32_t)__cvta_generic_to_shared(As);
    uint32_t sB = (uint32_t)__cvta_generic_to_shared(Bs);
    #pragma unroll
    for (int j = 0; j < 2; j++) {
        int f = tid + 256 * j;
        int m = f >> 2;
        int c8 = f & 3;
        int gm = bm + m;
        cp16(sA + (m * A_LDH + c8 * 8) * 2,
             A + (size_t)gm * HID + kc + c8 * 8, gm < M);
    }
    #pragma unroll
    for (int j = 0; j < 2; j++) {
        int f = tid + 256 * j;
        int k = f >> 4;
        int c8 = f & 15;
        cp16(sB + (k * B_LDH + c8 * 8) * 2,
             B + (size_t)(kc + k) * Ncols + bn + c8 * 8, true);
    }
    CP_COMMIT();
}

__device__ __forceinline__ void gemm_compute(
    const __half* As, const __half* Bs, int wm, int wn,
    wmma::fragment<wmma::accumulator, 16, 16, 16, float> (&cfrag)[2][4]) {
    #pragma unroll
    for (int ks = 0; ks < BK; ks += 16) {
        wmma::fragment<wmma::matrix_a, 16, 16, 16, __half, wmma::row_major> afrag[2];
        wmma::fragment<wmma::matrix_b, 16, 16, 16, __half, wmma::row_major> bfrag[4];
        #pragma unroll
        for (int i = 0; i < 2; i++)
            wmma::load_matrix_sync(afrag[i], &As[(wm * 32 + i * 16) * A_LDH + ks], A_LDH);
        #pragma unroll
        for (int j = 0; j < 4; j++)
            wmma::load_matrix_sync(bfrag[j], &Bs[ks * B_LDH + wn * 64 + j * 16], B_LDH);
        #pragma unroll
        for (int i = 0; i < 2; i++)
            #pragma unroll
            for (int j = 0; j < 4; j++)
                wmma::mma_sync(cfrag[i][j], afrag[i], bfrag[j], cfrag[i][j]);
    }
}

// HOUT=true: writes fp16 into plane blockIdx.y of g_qkvh ([NN_PAD][128] row-major).
template<bool HOUT>
__device__ __forceinline__ void gemm_tc_body(const __half* __restrict__ A,
                                             const __half* __restrict__ B,
                                             void* __restrict__ Cv,
                                             int M, int Ncols) {
    __shared__ alignas(16) __half smem[2 * STAGE_H];
    __half* As0 = smem;
    __half* Bs0 = smem + 128 * A_LDH;
    __half* As1 = smem + STAGE_H;
    __half* Bs1 = smem + STAGE_H + 128 * A_LDH;

    int tid = threadIdx.x;
    int wid = tid >> 5;
    int lane = tid & 31;
    int wm = wid & 3;
    int wn = wid >> 2;
    int bm = blockIdx.x * 128;
    int bn = blockIdx.y * 128;

    wmma::fragment<wmma::accumulator, 16, 16, 16, float> cfrag[2][4];
    #pragma unroll
    for (int i = 0; i < 2; i++)
        #pragma unroll
        for (int j = 0; j < 4; j++)
            wmma::fill_fragment(cfrag[i][j], 0.0f);

    gemm_issue(A, B, As0, Bs0, tid, bm, bn, 0, M, Ncols);
    gemm_issue(A, B, As1, Bs1, tid, bm, bn, BK, M, Ncols);
    CP_WAIT1(); __syncthreads();
    gemm_compute(As0, Bs0, wm, wn, cfrag);
    __syncthreads();
    gemm_issue(A, B, As0, Bs0, tid, bm, bn, 2 * BK, M, Ncols);
    CP_WAIT1(); __syncthreads();
    gemm_compute(As1, Bs1, wm, wn, cfrag);
    __syncthreads();
    gemm_issue(A, B, As1, Bs1, tid, bm, bn, 3 * BK, M, Ncols);
    CP_WAIT1(); __syncthreads();
    gemm_compute(As0, Bs0, wm, wn, cfrag);
    __syncthreads();
    CP_WAIT0(); __syncthreads();
    gemm_compute(As1, Bs1, wm, wn, cfrag);

    if (HOUT) {
        __syncthreads();
        __half* Ch = (__half*)Cv + (size_t)blockIdx.y * NN_PAD * HID;
        float* stage = (float*)smem;
        float* ws = stage + wid * 16 * S_LDM;
        #pragma unroll
        for (int i = 0; i < 2; i++) {
            #pragma unroll
            for (int j = 0; j < 4; j++)
                wmma::store_matrix_sync(ws + j * 16, cfrag[i][j], S_LDM, wmma::mem_row_major);
            __syncwarp();
            int gm = bm + wm * 32 + i * 16;
            int gn = wn * 64;
            #pragma unroll
            for (int rr = 0; rr < 16; rr++) {
                float2 v = *(float2*)(ws + rr * S_LDM + lane * 2);
                *(__half2*)(Ch + (size_t)(gm + rr) * HID + gn + lane * 2) =
                    __floats2half2_rn(v.x, v.y);
            }
            __syncwarp();
        }
    } else {
        float* C = (float*)Cv;
        #pragma unroll
        for (int i = 0; i < 2; i++) {
            int gm = bm + wm * 32 + i * 16;
            #pragma unroll
            for (int j = 0; j < 4; j++) {
                int gn = bn + wn * 64 + j * 16;
                wmma::store_matrix_sync(C + (size_t)gm * Ncols + gn, cfrag[i][j],
                                        Ncols, wmma::mem_row_major);
            }
        }
    }
}

__global__ void __launch_bounds__(256, 2) gemm_qkv_kernel() {
    gemm_tc_body<true>(g_xh, g_wbigh, g_qkvh, NN, NCOLS);
}
__global__ void __launch_bounds__(256, 2) gemm_proj_kernel() {
    gemm_tc_body<false>(g_acch, g_wprojh, g_proj, NN, HID);
}

// ---------------- fused convert + histogram (key = r*NN + dst) ----------------
__global__ void converthist_kernel(const int* __restrict__ ei_raw,
                                   const int* __restrict__ et_raw) {
    int i = blockIdx.x * blockDim.x + threadIdx.x;
    if (i >= EE) return;
    int s, d, r;
    if (g_is64) {
        s = ei_raw[2 * i];
        d = ei_raw[2 * (EE + i)];
        r = et_raw[2 * i];
    } else {
        s = ei_raw[i];
        d = ei_raw[EE + i];
        r = et_raw[i];
    }
    s = min(max(s, 0), NN - 1);
    d = min(max(d, 0), NN - 1);
    r = min(max(r, 0), RR - 1);
    g_src[i] = s;
    g_dst[i] = d;
    g_rel[i] = r;
    atomicAdd(&g_cnt[r * NN + d], 1);
}

// multi-block scan
__global__ void scan_p1_kernel() {
    __shared__ int wsum[8];
    int b = blockIdx.x;
    int t = threadIdx.x;
    int base = b * 1024 + t * 4;
    int4 v = make_int4(0, 0, 0, 0);
    if (base + 3 < NKEYS) {
        v = *(const int4*)&g_cnt[base];
    } else {
        if (base + 0 < NKEYS) v.x = g_cnt[base + 0];
        if (base + 1 < NKEYS) v.y = g_cnt[base + 1];
        if (base + 2 < NKEYS) v.z = g_cnt[base + 2];
        if (base + 3 < NKEYS) v.w = g_cnt[base + 3];
    }
    int tsum = v.x + v.y + v.z + v.w;
    int lane = t & 31, w = t >> 5;
    int sc = tsum;
    #pragma unroll
    for (int off = 1; off < 32; off <<= 1) {
        int n = __shfl_up_sync(0xFFFFFFFFu, sc, off);
        if (lane >= off) sc += n;
    }
    if (lane == 31) wsum[w] = sc;
    __syncthreads();
    if (t == 0) {
        int run = 0;
        #pragma unroll
        for (int i = 0; i < 8; i++) { int tmp = wsum[i]; wsum[i] = run; run += tmp; }
        g_bsum[b] = run;
    }
    __syncthreads();
    int excl = wsum[w] + sc - tsum;
    int4 o;
    o.x = excl;
    o.y = excl + v.x;
    o.z = excl + v.x + v.y;
    o.w = excl + v.x + v.y + v.z;
    if (base + 3 < NKEYS) {
        *(int4*)&g_offtmp[base] = o;
    } else {
        if (base + 0 < NKEYS) g_offtmp[base + 0] = o.x;
        if (base + 1 < NKEYS) g_offtmp[base + 1] = o.y;
        if (base + 2 < NKEYS) g_offtmp[base + 2] = o.z;
        if (base + 3 < NKEYS) g_offtmp[base + 3] = o.w;
    }
}

__global__ void scan_p2_kernel() {
    __shared__ int wsum[8];
    int t = threadIdx.x;
    int val = (t < NSBLK) ? g_bsum[t] : 0;
    int lane = t & 31, w = t >> 5;
    int sc = val;
    #pragma unroll
    for (int off = 1; off < 32; off <<= 1) {
        int n = __shfl_up_sync(0xFFFFFFFFu, sc, off);
        if (lane >= off) sc += n;
    }
    if (lane == 31) wsum[w] = sc;
    __syncthreads();
    if (t == 0) {
        int run = 0;
        #pragma unroll
        for (int i = 0; i < 8; i++) { int tmp = wsum[i]; wsum[i] = run; run += tmp; }
    }
    __syncthreads();
    int excl = wsum[w] + sc - val;
    if (t < NSBLK) g_boff[t] = excl;
}

__global__ void scan_p3_kernel() {
    int i = blockIdx.x * blockDim.x + threadIdx.x;
    if (i < NKEYS) {
        int v = g_offtmp[i] + g_boff[i >> 10];
        g_off[i] = v;
        g_cur[i] = v;
    }
    if (i == 0) g_off[NKEYS] = EE;
}

__global__ void scatter_kernel() {
    int i = blockIdx.x * blockDim.x + threadIdx.x;
    if (i < EE) {
        int key = g_rel[i] * NN + g_dst[i];
        int pos = atomicAdd(&g_cur[key], 1);
        g_srcs[pos] = g_src[i];
        g_key[pos]  = key;
    }
}

// ---------------- pass 1: 2 edges per warp (16 lanes each), uint4 gathers ----------------
// Lane l: sub = l>>4 selects edge, ll = l&15 covers dims [8*ll, 8*ll+8). head = ll>>1.
__global__ void edge_ev_kernel() {
    int w = (blockIdx.x * blockDim.x + threadIdx.x) >> 5;
    int l = threadIdx.x & 31;
    int sub = l >> 4;
    int ll = l & 15;
    int p = w * 2 + sub;
    if (p >= EE) return;
    int key = g_key[p];
    int src = g_srcs[p];
    int r = key / NN;
    int dst = key - r * NN;

    const __half* qp = g_qkvh + ((size_t)(r * 3 + 0) * NN_PAD + dst) * HID + ll * 8;
    const __half* kp = g_qkvh + ((size_t)(r * 3 + 1) * NN_PAD + src) * HID + ll * 8;
    uint4 qraw = *(const uint4*)qp;   // 8 halves
    uint4 kraw = *(const uint4*)kp;
    float2 q0 = __half22float2(*(__half2*)&qraw.x);
    float2 q1 = __half22float2(*(__half2*)&qraw.y);
    float2 q2 = __half22float2(*(__half2*)&qraw.z);
    float2 q3 = __half22float2(*(__half2*)&qraw.w);
    float2 k0 = __half22float2(*(__half2*)&kraw.x);
    float2 k1 = __half22float2(*(__half2*)&kraw.y);
    float2 k2 = __half22float2(*(__half2*)&kraw.z);
    float2 k3 = __half22float2(*(__half2*)&kraw.w);
    float pd = q0.x * k0.x + q0.y * k0.y + q1.x * k1.x + q1.y * k1.y
             + q2.x * k2.x + q2.y * k2.y + q3.x * k3.x + q3.y * k3.y;
    pd += __shfl_xor_sync(0xFFFFFFFFu, pd, 1);   // head = 16 dims = 2 lanes
    float ev = expf(pd * 0.25f);
    if ((ll & 1) == 0) g_ev[(size_t)p * NHEADS + (ll >> 1)] = ev;
}

// ---------------- pass 2: 2 dst per warp (16 lanes each), uint4 V gathers ----------------
// Lane l: half = l>>4 selects dst, ll = l&15 covers dims [8*ll, 8*ll+8). head = ll>>1.
__global__ void seg_accum_kernel() {
    int w = (blockIdx.x * blockDim.x + threadIdx.x) >> 5;
    int l = threadIdx.x & 31;
    int half = l >> 4;
    int ll = l & 15;
    int n = w * 2 + half;
    if (n >= NN) return;
    int h = ll >> 1;

    float out[8];
    #pragma unroll
    for (int i = 0; i < 8; i++) out[i] = 0.0f;

    #pragma unroll
    for (int r = 0; r < RR; r++) {
        int e0 = g_off[r * NN + n];
        int e1 = g_off[r * NN + n + 1];
        if (e0 >= e1) continue;
        const __half* vplane = g_qkvh + (size_t)(r * 3 + 2) * NN_PAD * HID;
        float sum = 0.0f;
        float acc[8];
        #pragma unroll
        for (int i = 0; i < 8; i++) acc[i] = 0.0f;
        #pragma unroll 4
        for (int e = e0; e < e1; e++) {
            int src = g_srcs[e];
            float ev = g_ev[(size_t)e * NHEADS + h];
            uint4 vraw = *(const uint4*)(vplane + (size_t)src * HID + ll * 8);
            float2 v0 = __half22float2(*(__half2*)&vraw.x);
            float2 v1 = __half22float2(*(__half2*)&vraw.y);
            float2 v2 = __half22float2(*(__half2*)&vraw.z);
            float2 v3 = __half22float2(*(__half2*)&vraw.w);
            sum += ev;
            acc[0] += ev * v0.x; acc[1] += ev * v0.y;
            acc[2] += ev * v1.x; acc[3] += ev * v1.y;
            acc[4] += ev * v2.x; acc[5] += ev * v2.y;
            acc[6] += ev * v3.x; acc[7] += ev * v3.y;
        }
        float inv = 1.0f / (sum + 1e-12f);
        #pragma unroll
        for (int i = 0; i < 8; i++) out[i] += acc[i] * inv;
    }
    // one coalesced 16B half store per lane
    uint4 packed;
    *(__half2*)&packed.x = __floats2half2_rn(out[0], out[1]);
    *(__half2*)&packed.y = __floats2half2_rn(out[2], out[3]);
    *(__half2*)&packed.z = __floats2half2_rn(out[4], out[5]);
    *(__half2*)&packed.w = __floats2half2_rn(out[6], out[7]);
    *(uint4*)(g_acch + (size_t)n * HID + ll * 8) = packed;
}

// ---------------- bias + residual + LayerNorm ----------------
__global__ void ln_kernel(const float* __restrict__ x,
                          const float* __restrict__ pb,
                          const float* __restrict__ gamma,
                          const float* __restrict__ beta,
                          float* __restrict__ out) {
    int n = (blockIdx.x * blockDim.x + threadIdx.x) >> 5;
    int l = threadIdx.x & 31;
    if (n >= NN) return;
    size_t base = (size_t)n * HID + l * 4;

    float4 p = *(const float4*)(g_proj + base);
    float4 xx = *(const float4*)(x + base);
    float4 b = *(const float4*)(pb + l * 4);
    float4 h;
    h.x = p.x + b.x + xx.x;
    h.y = p.y + b.y + xx.y;
    h.z = p.z + b.z + xx.z;
    h.w = p.w + b.w + xx.w;

    float s = h.x + h.y + h.z + h.w;
    #pragma unroll
    for (int off = 16; off >= 1; off >>= 1) s += __shfl_xor_sync(0xFFFFFFFFu, s, off);
    float mu = s * (1.0f / HID);

    float dx = h.x - mu, dy = h.y - mu, dz = h.z - mu, dw = h.w - mu;
    float v = dx * dx + dy * dy + dz * dz + dw * dw;
    #pragma unroll
    for (int off = 16; off >= 1; off >>= 1) v += __shfl_xor_sync(0xFFFFFFFFu, v, off);
    float inv = rsqrtf(v * (1.0f / HID) + LN_EPS);

    float4 g = *(const float4*)(gamma + l * 4);
    float4 be = *(const float4*)(beta + l * 4);
    float4 o;
    o.x = dx * inv * g.x + be.x;
    o.y = dy * inv * g.y + be.y;
    o.z = dz * inv * g.z + be.z;
    o.w = dw * inv * g.w + be.w;
    *(float4*)(out + base) = o;
}

// ---------------- launch ----------------
extern "C" void kernel_launch(void* const* d_in, const int* in_sizes, int n_in,
                              void* d_out, int out_size) {
    const float* x     = (const float*)d_in[0];
    const int*   ei    = (const int*)d_in[1];
    const int*   et    = (const int*)d_in[2];
    const float* WQ    = (const float*)d_in[3];
    const float* WK    = (const float*)d_in[4];
    const float* WV    = (const float*)d_in[5];
    const float* Wp    = (const float*)d_in[7];
    const float* pb    = (const float*)d_in[8];
    const float* gamma = (const float*)d_in[9];
    const float* beta  = (const float*)d_in[10];
    float* out = (float*)d_out;

    roundx_kernel<<<(NN * HID / 4 + 255) / 256, 256>>>(x);             // 0 (also zeros g_cnt)
    repack_kernel<<<(HID * NCOLS + 255) / 256, 256>>>(WQ, WK, WV, Wp); // 1
    detect_kernel<<<1, 32>>>(ei);                                      // 2

    dim3 g1(NN_PAD / 128, NCOLS / 128);                                // 391 x 15
    gemm_qkv_kernel<<<g1, 256>>>();                                    // 3  <-- profiled slot

    converthist_kernel<<<(EE + 255) / 256, 256>>>(ei, et);             // 4
    scan_p1_kernel<<<NSBLK, 256>>>();                                  // 5
    scan_p2_kernel<<<1, 256>>>();                                      // 6
    scan_p3_kernel<<<(NKEYS + 255) / 256, 256>>>();                    // 7
    scatter_kernel<<<(EE + 255) / 256, 256>>>();                       // 8

    int ev_blocks = (EE / 2 * 32 + 255) / 256;                         // 40000 (2 edges/warp)
    edge_ev_kernel<<<ev_blocks, 256>>>();                              // 9

    int sa_blocks = ((NN + 1) / 2 * 32 + 255) / 256;                   // 3125 (2 dst/warp)
    seg_accum_kernel<<<sa_blocks, 256>>>();                            // 10

    dim3 g2(NN_PAD / 128, 1);                                          // 391 x 1
    gemm_proj_kernel<<<g2, 256>>>();                                   // 11

    ln_kernel<<<(NN * 32 + 255) / 256, 256>>>(x, pb, gamma, beta, out);// 12
}